// round 6
// baseline (speedup 1.0000x reference)
#include <cuda_runtime.h>
#include <cuda_bf16.h>
#include <cstdint>

#define BATCH 2
#define SEQ   1024
#define HS    768
#define NH    12
#define HD    64
#define WIN   64
#define HALF  32
#define MTOK  (BATCH*SEQ)   // 2048
#define NX    (MTOK*HS)
#define NW    (HS*HS)

// ---------------------------------------------------------------------------
// Device-global scratch
// ---------------------------------------------------------------------------
__device__ float g_q[NX];
__device__ float g_k[NX];
__device__ float g_v[NX];
__device__ __nv_bfloat16 g_chi[NX], g_clo[NX];
__device__ __nv_bfloat16 g_wohi[NW], g_wolo[NW];
// int8 2-word planes
__device__ signed char g_x0[NX],  g_x1[NX];
__device__ signed char g_wq0[NW], g_wq1[NW];
__device__ signed char g_wk0[NW], g_wk1[NW];
__device__ signed char g_wv0[NW], g_wv1[NW];
__device__ unsigned g_amaxu[4];     // |X|, |Wq|, |Wk|, |Wv| as float bits

// ---------------------------------------------------------------------------
// PTX helpers
// ---------------------------------------------------------------------------
__device__ __forceinline__ uint32_t smem_u32(const void* p) {
    uint32_t a;
    asm("{ .reg .u64 t; cvta.to.shared.u64 t, %1; cvt.u32.u64 %0, t; }" : "=r"(a) : "l"(p));
    return a;
}
__device__ __forceinline__ void cp16(uint32_t dst, const void* src) {
    asm volatile("cp.async.cg.shared.global [%0], [%1], 16;" :: "r"(dst), "l"(src));
}
#define CP_COMMIT() asm volatile("cp.async.commit_group;")
#define CP_WAIT1()  asm volatile("cp.async.wait_group 1;")

__device__ __forceinline__ void ldsm4(uint32_t* r, uint32_t addr) {
    asm volatile("ldmatrix.sync.aligned.m8n8.x4.shared.b16 {%0,%1,%2,%3}, [%4];"
        : "=r"(r[0]), "=r"(r[1]), "=r"(r[2]), "=r"(r[3]) : "r"(addr));
}
__device__ __forceinline__ void mma_bf16(float* d, const uint32_t* a, uint32_t b0, uint32_t b1) {
    asm volatile(
        "mma.sync.aligned.m16n8k16.row.col.f32.bf16.bf16.f32 "
        "{%0,%1,%2,%3}, {%4,%5,%6,%7}, {%8,%9}, {%0,%1,%2,%3};"
        : "+f"(d[0]), "+f"(d[1]), "+f"(d[2]), "+f"(d[3])
        : "r"(a[0]), "r"(a[1]), "r"(a[2]), "r"(a[3]), "r"(b0), "r"(b1));
}
__device__ __forceinline__ void mma_s8(int* d, const uint32_t* a, uint32_t b0, uint32_t b1) {
    asm volatile(
        "mma.sync.aligned.m16n8k32.row.col.s32.s8.s8.s32 "
        "{%0,%1,%2,%3}, {%4,%5,%6,%7}, {%8,%9}, {%0,%1,%2,%3};"
        : "+r"(d[0]), "+r"(d[1]), "+r"(d[2]), "+r"(d[3])
        : "r"(a[0]), "r"(a[1]), "r"(a[2]), "r"(a[3]), "r"(b0), "r"(b1));
}

// ---------------------------------------------------------------------------
// amax + quantization + Wo split
// ---------------------------------------------------------------------------
__global__ void init_amax_kernel() {
    if (threadIdx.x < 4) g_amaxu[threadIdx.x] = 0u;
}

__global__ void amax_kernel(
    const float* __restrict__ X, const float* __restrict__ Wq,
    const float* __restrict__ Wk, const float* __restrict__ Wv)
{
    const int sec = blockIdx.y;
    const float* src; int n;
    if (sec == 0)      { src = X;  n = NX; }
    else if (sec == 1) { src = Wq; n = NW; }
    else if (sec == 2) { src = Wk; n = NW; }
    else               { src = Wv; n = NW; }
    float m = 0.f;
    for (int i = blockIdx.x * blockDim.x + threadIdx.x; i < n; i += gridDim.x * blockDim.x)
        m = fmaxf(m, fabsf(src[i]));
    #pragma unroll
    for (int o = 16; o; o >>= 1) m = fmaxf(m, __shfl_xor_sync(0xFFFFFFFFu, m, o));
    __shared__ float red[8];
    if ((threadIdx.x & 31) == 0) red[threadIdx.x >> 5] = m;
    __syncthreads();
    if (threadIdx.x < 8) {
        float v = red[threadIdx.x];
        #pragma unroll
        for (int o = 4; o; o >>= 1) v = fmaxf(v, __shfl_xor_sync(0xFFu, v, o));
        if (threadIdx.x == 0) atomicMax(&g_amaxu[sec], __float_as_uint(v));
    }
}

__device__ __forceinline__ void q2w(float x, float inv, signed char& a, signed char& b) {
    float r  = x * inv;
    float q0 = rintf(r);
    a = (signed char)(int)q0;
    b = (signed char)(int)rintf((r - q0) * 128.f);
}

__global__ void quant_kernel(
    const float* __restrict__ X, const float* __restrict__ Wq,
    const float* __restrict__ Wk, const float* __restrict__ Wv,
    const float* __restrict__ Wo)
{
    const int tot4 = (NX + 4 * NW) / 4;
    for (int i4 = blockIdx.x * blockDim.x + threadIdx.x; i4 < tot4; i4 += gridDim.x * blockDim.x) {
        int i = i4 * 4;
        if (i < NX + 3 * NW) {
            const float* src; signed char *p0, *p1; int r, sec;
            if (i < NX) { src = X; p0 = g_x0; p1 = g_x1; r = i; sec = 0; }
            else {
                int j = i - NX; int w = j / NW; r = j - w * NW;
                if (w == 0)      { src = Wq; p0 = g_wq0; p1 = g_wq1; sec = 1; }
                else if (w == 1) { src = Wk; p0 = g_wk0; p1 = g_wk1; sec = 2; }
                else             { src = Wv; p0 = g_wv0; p1 = g_wv1; sec = 3; }
            }
            float am = __uint_as_float(g_amaxu[sec]);
            float inv = am > 0.f ? 127.f / am : 0.f;
            float4 x = *(const float4*)(src + r);
            char4 a, b;
            q2w(x.x, inv, a.x, b.x);
            q2w(x.y, inv, a.y, b.y);
            q2w(x.z, inv, a.z, b.z);
            q2w(x.w, inv, a.w, b.w);
            *(char4*)(p0 + r) = a;
            *(char4*)(p1 + r) = b;
        } else {
            // Wo bf16 hi/lo split
            int r = i - (NX + 3 * NW);
            float4 x = *(const float4*)(Wo + r);
            float xs[4] = {x.x, x.y, x.z, x.w};
            #pragma unroll
            for (int t = 0; t < 4; t++) {
                __nv_bfloat16 h = __float2bfloat16(xs[t]);
                g_wohi[r + t] = h;
                g_wolo[r + t] = __float2bfloat16(xs[t] - __bfloat162float(h));
            }
        }
    }
}

// ---------------------------------------------------------------------------
// QKV GEMM, int8 2-word, 3-pass IMMA.  C = s_a s_b (accA + accB/128) + bias
// CTA 128x64, 8 warps (4M x 2N), warp tile 32x32, K-chunk 64 int8 = 64B rows
// padded to 80B (same conflict-free geometry as the bf16 tiles).
// 3-stage cp.async pipeline, one __syncthreads per iteration.
// ---------------------------------------------------------------------------
#define QSTG_B  30720      // (128+128+64+64) rows * 80B
#define SMEM_QKV (3 * QSTG_B)
#define NST 12             // 768 / 64

__device__ __forceinline__ void load_q_chunk(
    uint32_t sb, int st, int kc,
    const signed char* __restrict__ A0, const signed char* __restrict__ A1,
    const signed char* __restrict__ B0, const signed char* __restrict__ B1,
    int by, int bx, int tid)
{
    const int k0 = kc * 64;
    const uint32_t base = sb + (uint32_t)st * QSTG_B;
    #pragma unroll
    for (int it = 0; it < 6; it++) {
        int idx = it * 256 + tid;          // 0..1535
        int r   = idx >> 2;                // 0..383
        int cb  = idx & 3;                 // 16B chunk
        const signed char* src; uint32_t toff; int row;
        if (r < 128)      { src = A0 + (size_t)(by * 128 + r) * HS;         toff = 0;     row = r; }
        else if (r < 256) { src = A1 + (size_t)(by * 128 + (r - 128)) * HS; toff = 10240; row = r - 128; }
        else if (r < 320) { src = B0 + (size_t)(bx * 64 + (r - 256)) * HS;  toff = 20480; row = r - 256; }
        else              { src = B1 + (size_t)(bx * 64 + (r - 320)) * HS;  toff = 25600; row = r - 320; }
        cp16(base + toff + (uint32_t)row * 80 + (uint32_t)cb * 16, src + k0 + cb * 16);
    }
}

__global__ __launch_bounds__(256, 2) void qkv_imma_kernel(
    const float* __restrict__ bq, const float* __restrict__ bk, const float* __restrict__ bv)
{
    const signed char *B0, *B1; const float* bias; float* C;
    const int z = blockIdx.z;
    if (z == 0)      { B0 = g_wq0; B1 = g_wq1; bias = bq; C = g_q; }
    else if (z == 1) { B0 = g_wk0; B1 = g_wk1; bias = bk; C = g_k; }
    else             { B0 = g_wv0; B1 = g_wv1; bias = bv; C = g_v; }

    extern __shared__ char smem[];
    const uint32_t sb = smem_u32(smem);
    const int tid  = threadIdx.x;
    const int lane = tid & 31;
    const int warp = tid >> 5;
    const int wm   = warp & 3;          // 0..3  -> M*32
    const int wn   = warp >> 2;         // 0..1  -> N*32
    const int bx = blockIdx.x, by = blockIdx.y;

    int accA[2][4][4], accB[2][4][4];
    #pragma unroll
    for (int i = 0; i < 2; i++)
        #pragma unroll
        for (int j = 0; j < 4; j++)
            #pragma unroll
            for (int r = 0; r < 4; r++) { accA[i][j][r] = 0; accB[i][j][r] = 0; }

    load_q_chunk(sb, 0, 0, g_x0, g_x1, B0, B1, by, bx, tid); CP_COMMIT();
    load_q_chunk(sb, 1, 1, g_x0, g_x1, B0, B1, by, bx, tid); CP_COMMIT();

    const uint32_t arow = (uint32_t)(lane & 15);
    const uint32_t asel = (uint32_t)(lane >> 4) * 16;

    for (int kc = 0; kc < NST; kc++) {
        CP_WAIT1();
        __syncthreads();
        if (kc + 2 < NST) {
            load_q_chunk(sb, (kc + 2) % 3, kc + 2, g_x0, g_x1, B0, B1, by, bx, tid);
            CP_COMMIT();
        }
        const uint32_t base = sb + (uint32_t)(kc % 3) * QSTG_B;

        #pragma unroll
        for (int ks = 0; ks < 2; ks++) {
            const uint32_t colb = (uint32_t)ks * 32 + asel;
            uint32_t ah[2][4], al[2][4], bh[2][4], bl[2][4];
            #pragma unroll
            for (int i = 0; i < 2; i++) {
                uint32_t ro = (uint32_t)(wm * 32 + i * 16) + arow;
                ldsm4(ah[i], base +         ro * 80 + colb);
                ldsm4(al[i], base + 10240 + ro * 80 + colb);
            }
            #pragma unroll
            for (int jj = 0; jj < 2; jj++) {
                uint32_t ro = (uint32_t)(wn * 32 + jj * 16) + arow;
                ldsm4(bh[jj], base + 20480 + ro * 80 + colb);
                ldsm4(bl[jj], base + 25600 + ro * 80 + colb);
            }
            // pass 1: q0*q0 -> accA
            #pragma unroll
            for (int i = 0; i < 2; i++)
                #pragma unroll
                for (int jj = 0; jj < 2; jj++) {
                    mma_s8(accA[i][jj * 2 + 0], ah[i], bh[jj][0], bh[jj][2]);
                    mma_s8(accA[i][jj * 2 + 1], ah[i], bh[jj][1], bh[jj][3]);
                }
            // pass 2+3: cross terms -> accB
            #pragma unroll
            for (int i = 0; i < 2; i++)
                #pragma unroll
                for (int jj = 0; jj < 2; jj++) {
                    mma_s8(accB[i][jj * 2 + 0], ah[i], bl[jj][0], bl[jj][2]);
                    mma_s8(accB[i][jj * 2 + 1], ah[i], bl[jj][1], bl[jj][3]);
                }
            #pragma unroll
            for (int i = 0; i < 2; i++)
                #pragma unroll
                for (int jj = 0; jj < 2; jj++) {
                    mma_s8(accB[i][jj * 2 + 0], al[i], bh[jj][0], bh[jj][2]);
                    mma_s8(accB[i][jj * 2 + 1], al[i], bh[jj][1], bh[jj][3]);
                }
        }
        __syncthreads();
    }

    const float s = (__uint_as_float(g_amaxu[0]) * (1.f / 127.f)) *
                    (__uint_as_float(g_amaxu[1 + z]) * (1.f / 127.f));
    const int g  = lane >> 2;
    const int tg = lane & 3;
    #pragma unroll
    for (int i = 0; i < 2; i++) {
        const int row = by * 128 + wm * 32 + i * 16 + g;
        #pragma unroll
        for (int j = 0; j < 4; j++) {
            const int col = bx * 64 + wn * 32 + j * 8 + tg * 2;
            const float b0 = bias[col], b1 = bias[col + 1];
            float v0 = s * ((float)accA[i][j][0] + (float)accB[i][j][0] * 0.0078125f) + b0;
            float v1 = s * ((float)accA[i][j][1] + (float)accB[i][j][1] * 0.0078125f) + b1;
            float v2 = s * ((float)accA[i][j][2] + (float)accB[i][j][2] * 0.0078125f) + b0;
            float v3 = s * ((float)accA[i][j][3] + (float)accB[i][j][3] * 0.0078125f) + b1;
            *(float2*)&C[(size_t)row * HS + col]       = make_float2(v0, v1);
            *(float2*)&C[(size_t)(row + 8) * HS + col] = make_float2(v2, v3);
        }
    }
}

// ---------------------------------------------------------------------------
// Output projection: bf16x3 HMMA, 3-stage pipeline.
// CTA 128x64, 8 warps (2M x 4N), warp tile 64x16.
// ---------------------------------------------------------------------------
#define OSTG_B  30720
#define SMEM_OUT (3 * OSTG_B)
#define ONST 24            // 768 / 32

__device__ __forceinline__ void load_o_chunk(
    uint32_t sb, int st, int kc,
    const __nv_bfloat16* __restrict__ Ahi, const __nv_bfloat16* __restrict__ Alo,
    const __nv_bfloat16* __restrict__ Bhi, const __nv_bfloat16* __restrict__ Blo,
    int by, int bx, int tid)
{
    const int k0 = kc * 32;
    const uint32_t base = sb + (uint32_t)st * OSTG_B;
    #pragma unroll
    for (int it = 0; it < 6; it++) {
        int idx = it * 256 + tid;
        int r   = idx >> 2;
        int cb  = idx & 3;
        const __nv_bfloat16* src; uint32_t toff; int row;
        if (r < 128)      { src = Ahi + (size_t)(by * 128 + r) * HS;         toff = 0;     row = r; }
        else if (r < 256) { src = Alo + (size_t)(by * 128 + (r - 128)) * HS; toff = 10240; row = r - 128; }
        else if (r < 320) { src = Bhi + (size_t)(bx * 64 + (r - 256)) * HS;  toff = 20480; row = r - 256; }
        else              { src = Blo + (size_t)(bx * 64 + (r - 320)) * HS;  toff = 25600; row = r - 320; }
        cp16(base + toff + (uint32_t)row * 80 + (uint32_t)cb * 16, src + k0 + cb * 8);
    }
}

__global__ __launch_bounds__(256, 2) void out_kernel(
    const float* __restrict__ bo, float* __restrict__ Cout)
{
    extern __shared__ char smem[];
    const uint32_t sb = smem_u32(smem);
    const int tid  = threadIdx.x;
    const int lane = tid & 31;
    const int warp = tid >> 5;
    const int wm   = warp & 1;
    const int wn   = warp >> 1;
    const int bx = blockIdx.x, by = blockIdx.y;

    float acc[4][2][4];
    #pragma unroll
    for (int i = 0; i < 4; i++)
        #pragma unroll
        for (int j = 0; j < 2; j++)
            #pragma unroll
            for (int r = 0; r < 4; r++) acc[i][j][r] = 0.f;

    load_o_chunk(sb, 0, 0, g_chi, g_clo, g_wohi, g_wolo, by, bx, tid); CP_COMMIT();
    load_o_chunk(sb, 1, 1, g_chi, g_clo, g_wohi, g_wolo, by, bx, tid); CP_COMMIT();

    const uint32_t arow = (uint32_t)(lane & 15);
    const uint32_t asel = (uint32_t)(lane >> 4) * 16;

    for (int kc = 0; kc < ONST; kc++) {
        CP_WAIT1();
        __syncthreads();
        if (kc + 2 < ONST) {
            load_o_chunk(sb, (kc + 2) % 3, kc + 2, g_chi, g_clo, g_wohi, g_wolo, by, bx, tid);
            CP_COMMIT();
        }
        const uint32_t base = sb + (uint32_t)(kc % 3) * OSTG_B;

        #pragma unroll
        for (int ks = 0; ks < 2; ks++) {
            const uint32_t colb = (uint32_t)ks * 32 + asel;
            uint32_t ah[4][4], al[4][4], bh[4], bl[4];
            #pragma unroll
            for (int i = 0; i < 4; i++) {
                uint32_t ro = (uint32_t)(wm * 64 + i * 16) + arow;
                ldsm4(ah[i], base +         ro * 80 + colb);
                ldsm4(al[i], base + 10240 + ro * 80 + colb);
            }
            {
                uint32_t ro = (uint32_t)(wn * 16) + arow;
                ldsm4(bh, base + 20480 + ro * 80 + colb);
                ldsm4(bl, base + 25600 + ro * 80 + colb);
            }
            #pragma unroll
            for (int i = 0; i < 4; i++) {
                mma_bf16(acc[i][0], ah[i], bh[0], bh[2]);
                mma_bf16(acc[i][1], ah[i], bh[1], bh[3]);
            }
            #pragma unroll
            for (int i = 0; i < 4; i++) {
                mma_bf16(acc[i][0], ah[i], bl[0], bl[2]);
                mma_bf16(acc[i][1], ah[i], bl[1], bl[3]);
            }
            #pragma unroll
            for (int i = 0; i < 4; i++) {
                mma_bf16(acc[i][0], al[i], bh[0], bh[2]);
                mma_bf16(acc[i][1], al[i], bh[1], bh[3]);
            }
        }
        __syncthreads();
    }

    const int g  = lane >> 2;
    const int tg = lane & 3;
    #pragma unroll
    for (int i = 0; i < 4; i++) {
        const int row = by * 128 + wm * 64 + i * 16 + g;
        #pragma unroll
        for (int j = 0; j < 2; j++) {
            const int col = bx * 64 + wn * 16 + j * 8 + tg * 2;
            const float b0 = bo[col], b1 = bo[col + 1];
            *(float2*)&Cout[(size_t)row * HS + col] =
                make_float2(acc[i][j][0] + b0, acc[i][j][1] + b1);
            *(float2*)&Cout[(size_t)(row + 8) * HS + col] =
                make_float2(acc[i][j][2] + b0, acc[i][j][3] + b1);
        }
    }
}

// ---------------------------------------------------------------------------
// Sliding-window attention (unchanged from R4).
// ---------------------------------------------------------------------------
#define AR 95
#define KST 68
#define SMEM_ATTN ((2*AR*KST + 32*64) * 4)

__global__ __launch_bounds__(1024) void attn_kernel()
{
    extern __shared__ float sm[];
    float (*Ks)[KST] = (float(*)[KST])sm;
    float (*Vs)[KST] = (float(*)[KST])(sm + AR * KST);
    float (*Ps)[64]  = (float(*)[64])(sm + 2 * AR * KST);

    const int s0 = blockIdx.x * 32;
    const int h  = blockIdx.y;
    const int b  = blockIdx.z;
    const int tid = threadIdx.x;
    const int base = (b * SEQ) * HS + h * HD;

    for (int i = tid; i < AR * 16; i += 1024) {
        int r = i >> 4, c4 = (i & 15) * 4;
        int j = s0 - HALF + r;
        float4 kv = make_float4(0.f, 0.f, 0.f, 0.f), vv = kv;
        if (j >= 0 && j < SEQ) {
            int off = base + j * HS + c4;
            kv = *(const float4*)&g_k[off];
            vv = *(const float4*)&g_v[off];
        }
        *(float4*)&Ks[r][c4] = kv;
        *(float4*)&Vs[r][c4] = vv;
    }
    __syncthreads();

    const int wq   = tid >> 5;
    const int lane = tid & 31;
    const float* qrow = g_q + base + (s0 + wq) * HS;

    float sc0 = 0.f, sc1 = 0.f;
    #pragma unroll
    for (int d4 = 0; d4 < 16; d4++) {
        float4 q  = __ldg((const float4*)(qrow + d4 * 4));
        float4 k0 = *(const float4*)&Ks[wq + lane][d4 * 4];
        float4 k1 = *(const float4*)&Ks[wq + lane + 32][d4 * 4];
        sc0 += q.x * k0.x + q.y * k0.y + q.z * k0.z + q.w * k0.w;
        sc1 += q.x * k1.x + q.y * k1.y + q.z * k1.z + q.w * k1.w;
    }
    sc0 *= 0.125f;
    sc1 *= 0.125f;

    float m = fmaxf(sc0, sc1);
    #pragma unroll
    for (int o = 16; o; o >>= 1) m = fmaxf(m, __shfl_xor_sync(0xFFFFFFFFu, m, o));
    float e0 = __expf(sc0 - m);
    float e1 = __expf(sc1 - m);
    float sum = e0 + e1;
    #pragma unroll
    for (int o = 16; o; o >>= 1) sum += __shfl_xor_sync(0xFFFFFFFFu, sum, o);
    float inv = 1.f / sum;
    Ps[wq][lane]      = e0 * inv;
    Ps[wq][lane + 32] = e1 * inv;
    __syncwarp();

    float c0 = 0.f, c1 = 0.f;
    #pragma unroll
    for (int w = 0; w < 64; w++) {
        float p = Ps[wq][w];
        float2 v = *(const float2*)&Vs[wq + w][2 * lane];
        c0 += p * v.x;
        c1 += p * v.y;
    }
    const int orow = base + (s0 + wq) * HS + 2 * lane;
    __nv_bfloat162 hi2, lo2;
    hi2.x = __float2bfloat16(c0);
    hi2.y = __float2bfloat16(c1);
    lo2.x = __float2bfloat16(c0 - __bfloat162float(hi2.x));
    lo2.y = __float2bfloat16(c1 - __bfloat162float(hi2.y));
    *(__nv_bfloat162*)&g_chi[orow] = hi2;
    *(__nv_bfloat162*)&g_clo[orow] = lo2;
}

// ---------------------------------------------------------------------------
extern "C" void kernel_launch(void* const* d_in, const int* in_sizes, int n_in,
                              void* d_out, int out_size)
{
    const float* X  = (const float*)d_in[0];
    const float* Wq = (const float*)d_in[1];
    const float* bq = (const float*)d_in[2];
    const float* Wk = (const float*)d_in[3];
    const float* bk = (const float*)d_in[4];
    const float* Wv = (const float*)d_in[5];
    const float* bv = (const float*)d_in[6];
    const float* Wo = (const float*)d_in[7];
    const float* bo = (const float*)d_in[8];
    float* out = (float*)d_out;

    static bool attr_done = false;
    if (!attr_done) {
        cudaFuncSetAttribute(qkv_imma_kernel, cudaFuncAttributeMaxDynamicSharedMemorySize, SMEM_QKV);
        cudaFuncSetAttribute(out_kernel,      cudaFuncAttributeMaxDynamicSharedMemorySize, SMEM_OUT);
        cudaFuncSetAttribute(attn_kernel,     cudaFuncAttributeMaxDynamicSharedMemorySize, SMEM_ATTN);
        attr_done = true;
    }

    init_amax_kernel<<<1, 32>>>();
    amax_kernel<<<dim3(96, 4), 256>>>(X, Wq, Wk, Wv);
    quant_kernel<<<816, 256>>>(X, Wq, Wk, Wv, Wo);

    dim3 qkv_grid(HS / 64, MTOK / 128, 3);     // (12, 16, 3)
    qkv_imma_kernel<<<qkv_grid, 256, SMEM_QKV>>>(bq, bk, bv);

    dim3 attn_grid(SEQ / 32, NH, BATCH);       // (32, 12, 2)
    attn_kernel<<<attn_grid, 1024, SMEM_ATTN>>>();

    dim3 out_grid(HS / 64, MTOK / 128, 1);     // (12, 16)
    out_kernel<<<out_grid, 256, SMEM_OUT>>>(bo, out);
}

// round 7
// speedup vs baseline: 1.4518x; 1.4518x over previous
#include <cuda_runtime.h>
#include <cuda_bf16.h>
#include <cstdint>

#define BATCH 2
#define SEQ   1024
#define HS    768
#define NH    12
#define HD    64
#define WIN   64
#define HALF  32
#define MTOK  (BATCH*SEQ)   // 2048
#define NX    (MTOK*HS)
#define NW    (HS*HS)

#define BM 128
#define BN 128
#define BK 32
#define NKC (HS / BK)       // 24

// ---------------------------------------------------------------------------
// Device-global scratch
// ---------------------------------------------------------------------------
__device__ float g_q[NX];
__device__ float g_k[NX];
__device__ float g_v[NX];
__device__ __nv_bfloat16 g_xhi[NX], g_xlo[NX];
__device__ __nv_bfloat16 g_chi[NX], g_clo[NX];
__device__ __nv_bfloat16 g_wqhi[NW], g_wqlo[NW];
__device__ __nv_bfloat16 g_wkhi[NW], g_wklo[NW];
__device__ __nv_bfloat16 g_wvhi[NW], g_wvlo[NW];
__device__ __nv_bfloat16 g_wohi[NW], g_wolo[NW];

// ---------------------------------------------------------------------------
// PTX helpers
// ---------------------------------------------------------------------------
__device__ __forceinline__ uint32_t smem_u32(const void* p) {
    uint32_t a;
    asm("{ .reg .u64 t; cvta.to.shared.u64 t, %1; cvt.u32.u64 %0, t; }" : "=r"(a) : "l"(p));
    return a;
}
__device__ __forceinline__ void cp16(uint32_t dst, const void* src) {
    asm volatile("cp.async.cg.shared.global [%0], [%1], 16;" :: "r"(dst), "l"(src));
}
#define CP_COMMIT() asm volatile("cp.async.commit_group;")
#define CP_WAIT1()  asm volatile("cp.async.wait_group 1;")

__device__ __forceinline__ void ldsm4(uint32_t* r, uint32_t addr) {
    asm volatile("ldmatrix.sync.aligned.m8n8.x4.shared.b16 {%0,%1,%2,%3}, [%4];"
        : "=r"(r[0]), "=r"(r[1]), "=r"(r[2]), "=r"(r[3]) : "r"(addr));
}
__device__ __forceinline__ void mma_bf16(float* d, const uint32_t* a, uint32_t b0, uint32_t b1) {
    asm volatile(
        "mma.sync.aligned.m16n8k16.row.col.f32.bf16.bf16.f32 "
        "{%0,%1,%2,%3}, {%4,%5,%6,%7}, {%8,%9}, {%0,%1,%2,%3};"
        : "+f"(d[0]), "+f"(d[1]), "+f"(d[2]), "+f"(d[3])
        : "r"(a[0]), "r"(a[1]), "r"(a[2]), "r"(a[3]), "r"(b0), "r"(b1));
}

// ---------------------------------------------------------------------------
// smem: 4 planes per stage, 128 rows each, row = 32 bf16 = 64B padded to 80B.
//   Ahi @ 0, Alo @ 10240, Bhi @ 20480, Blo @ 30720.  Stage = 40960 B.
// ---------------------------------------------------------------------------
#define STAGE_B  40960
#define SMEM_GEMM (3 * STAGE_B)

__device__ __forceinline__ void load_chunk(
    uint32_t sb, int st, int kc,
    const __nv_bfloat16* __restrict__ Ahi, const __nv_bfloat16* __restrict__ Alo,
    const __nv_bfloat16* __restrict__ Bhi, const __nv_bfloat16* __restrict__ Blo,
    int by, int bx, int tid)
{
    const int k0 = kc * BK;
    const uint32_t base = sb + (uint32_t)st * STAGE_B;
    #pragma unroll
    for (int it = 0; it < 8; it++) {
        int idx = it * 256 + tid;          // 0..2047
        int r   = idx >> 2;                // 0..511
        int cb  = idx & 3;                 // 16B chunk in 64B row
        const __nv_bfloat16* src; uint32_t toff; int row;
        if (r < 128)      { src = Ahi + (size_t)(by * BM + r) * HS;         toff = 0;     row = r; }
        else if (r < 256) { src = Alo + (size_t)(by * BM + (r - 128)) * HS; toff = 10240; row = r - 128; }
        else if (r < 384) { src = Bhi + (size_t)(bx * BN + (r - 256)) * HS; toff = 20480; row = r - 256; }
        else              { src = Blo + (size_t)(bx * BN + (r - 384)) * HS; toff = 30720; row = r - 384; }
        cp16(base + toff + (uint32_t)row * 80 + (uint32_t)cb * 16, src + k0 + cb * 8);
    }
}

// ---------------------------------------------------------------------------
// bf16x3 HMMA GEMM: C[M,N] = (Ahi+Alo)[M,K] @ (Bhi+Blo)[N,K]^T + bias
// CTA 128x128, 8 warps (2M x 4N), warp tile 64x32.
// 3-stage cp.async pipeline, one __syncthreads per k-iter.
// ---------------------------------------------------------------------------
__device__ __forceinline__ void hgemm(
    const __nv_bfloat16* __restrict__ Ahi, const __nv_bfloat16* __restrict__ Alo,
    const __nv_bfloat16* __restrict__ Bhi, const __nv_bfloat16* __restrict__ Blo,
    const float* __restrict__ bias, float* __restrict__ C,
    int bx, int by)
{
    extern __shared__ char smem[];
    const uint32_t sb = smem_u32(smem);
    const int tid  = threadIdx.x;
    const int lane = tid & 31;
    const int warp = tid >> 5;
    const int wm   = warp & 1;          // 0..1 -> M*64
    const int wn   = warp >> 1;         // 0..3 -> N*32

    float acc[4][4][4];
    #pragma unroll
    for (int i = 0; i < 4; i++)
        #pragma unroll
        for (int j = 0; j < 4; j++)
            #pragma unroll
            for (int r = 0; r < 4; r++) acc[i][j][r] = 0.f;

    load_chunk(sb, 0, 0, Ahi, Alo, Bhi, Blo, by, bx, tid); CP_COMMIT();
    load_chunk(sb, 1, 1, Ahi, Alo, Bhi, Blo, by, bx, tid); CP_COMMIT();

    const uint32_t arow = (uint32_t)(lane & 15);
    const uint32_t asel = (uint32_t)(lane >> 4) * 16;

    for (int kc = 0; kc < NKC; kc++) {
        CP_WAIT1();
        __syncthreads();
        if (kc + 2 < NKC) {
            load_chunk(sb, (kc + 2) % 3, kc + 2, Ahi, Alo, Bhi, Blo, by, bx, tid);
            CP_COMMIT();
        }
        const uint32_t base = sb + (uint32_t)(kc % 3) * STAGE_B;

        #pragma unroll
        for (int ks = 0; ks < 2; ks++) {
            const uint32_t colb = (uint32_t)ks * 32 + asel;
            uint32_t ah[4][4], al[4][4], bh[2][4], bl[2][4];
            #pragma unroll
            for (int i = 0; i < 4; i++) {
                uint32_t ro = (uint32_t)(wm * 64 + i * 16) + arow;
                ldsm4(ah[i], base +         ro * 80 + colb);
                ldsm4(al[i], base + 10240 + ro * 80 + colb);
            }
            #pragma unroll
            for (int jj = 0; jj < 2; jj++) {
                uint32_t ro = (uint32_t)(wn * 32 + jj * 16) + arow;
                ldsm4(bh[jj], base + 20480 + ro * 80 + colb);
                ldsm4(bl[jj], base + 30720 + ro * 80 + colb);
            }
            // pass 1: hi*hi
            #pragma unroll
            for (int i = 0; i < 4; i++)
                #pragma unroll
                for (int jj = 0; jj < 2; jj++) {
                    mma_bf16(acc[i][jj * 2 + 0], ah[i], bh[jj][0], bh[jj][2]);
                    mma_bf16(acc[i][jj * 2 + 1], ah[i], bh[jj][1], bh[jj][3]);
                }
            // pass 2: hi*lo
            #pragma unroll
            for (int i = 0; i < 4; i++)
                #pragma unroll
                for (int jj = 0; jj < 2; jj++) {
                    mma_bf16(acc[i][jj * 2 + 0], ah[i], bl[jj][0], bl[jj][2]);
                    mma_bf16(acc[i][jj * 2 + 1], ah[i], bl[jj][1], bl[jj][3]);
                }
            // pass 3: lo*hi
            #pragma unroll
            for (int i = 0; i < 4; i++)
                #pragma unroll
                for (int jj = 0; jj < 2; jj++) {
                    mma_bf16(acc[i][jj * 2 + 0], al[i], bh[jj][0], bh[jj][2]);
                    mma_bf16(acc[i][jj * 2 + 1], al[i], bh[jj][1], bh[jj][3]);
                }
        }
        __syncthreads();
    }

    const int g  = lane >> 2;
    const int tg = lane & 3;
    #pragma unroll
    for (int i = 0; i < 4; i++) {
        const int row = by * BM + wm * 64 + i * 16 + g;
        #pragma unroll
        for (int j = 0; j < 4; j++) {
            const int col = bx * BN + wn * 32 + j * 8 + tg * 2;
            const float b0 = bias[col], b1 = bias[col + 1];
            *(float2*)&C[(size_t)row * HS + col] =
                make_float2(acc[i][j][0] + b0, acc[i][j][1] + b1);
            *(float2*)&C[(size_t)(row + 8) * HS + col] =
                make_float2(acc[i][j][2] + b0, acc[i][j][3] + b1);
        }
    }
}

__global__ __launch_bounds__(256, 1) void qkv_kernel(
    const float* __restrict__ bq, const float* __restrict__ bk, const float* __restrict__ bv)
{
    const __nv_bfloat16 *Bh, *Bl; const float* b; float* C;
    if (blockIdx.z == 0)      { Bh = g_wqhi; Bl = g_wqlo; b = bq; C = g_q; }
    else if (blockIdx.z == 1) { Bh = g_wkhi; Bl = g_wklo; b = bk; C = g_k; }
    else                      { Bh = g_wvhi; Bl = g_wvlo; b = bv; C = g_v; }
    hgemm(g_xhi, g_xlo, Bh, Bl, b, C, blockIdx.x, blockIdx.y);
}

__global__ __launch_bounds__(256, 1) void out_kernel(
    const float* __restrict__ bo, float* __restrict__ out)
{
    hgemm(g_chi, g_clo, g_wohi, g_wolo, bo, out, blockIdx.x, blockIdx.y);
}

// ---------------------------------------------------------------------------
// Split fp32 -> bf16 hi/lo (X + 4 weights).
// ---------------------------------------------------------------------------
__global__ void split_kernel(
    const float* __restrict__ X,
    const float* __restrict__ Wq, const float* __restrict__ Wk,
    const float* __restrict__ Wv, const float* __restrict__ Wo)
{
    const int tot4 = (NX + 4 * NW) / 4;
    for (int i4 = blockIdx.x * blockDim.x + threadIdx.x; i4 < tot4; i4 += gridDim.x * blockDim.x) {
        int i = i4 * 4;
        const float* src; __nv_bfloat16 *hi, *lo; int r;
        if (i < NX) { src = X; hi = g_xhi; lo = g_xlo; r = i; }
        else {
            int j = i - NX; int w = j / NW; r = j - w * NW;
            if (w == 0)      { src = Wq; hi = g_wqhi; lo = g_wqlo; }
            else if (w == 1) { src = Wk; hi = g_wkhi; lo = g_wklo; }
            else if (w == 2) { src = Wv; hi = g_wvhi; lo = g_wvlo; }
            else             { src = Wo; hi = g_wohi; lo = g_wolo; }
        }
        float4 x = *(const float4*)(src + r);
        float xs[4] = {x.x, x.y, x.z, x.w};
        __nv_bfloat162 h2[2], l2[2];
        #pragma unroll
        for (int t = 0; t < 4; t++) {
            __nv_bfloat16 h = __float2bfloat16(xs[t]);
            ((__nv_bfloat16*)h2)[t] = h;
            ((__nv_bfloat16*)l2)[t] = __float2bfloat16(xs[t] - __bfloat162float(h));
        }
        *(__nv_bfloat162*)(hi + r)     = h2[0];
        *(__nv_bfloat162*)(hi + r + 2) = h2[1];
        *(__nv_bfloat162*)(lo + r)     = l2[0];
        *(__nv_bfloat162*)(lo + r + 2) = l2[1];
    }
}

// ---------------------------------------------------------------------------
// Sliding-window attention (proven R4 version).
// ---------------------------------------------------------------------------
#define AR 95
#define KST 68
#define SMEM_ATTN ((2*AR*KST + 32*64) * 4)

__global__ __launch_bounds__(1024) void attn_kernel()
{
    extern __shared__ float sm[];
    float (*Ks)[KST] = (float(*)[KST])sm;
    float (*Vs)[KST] = (float(*)[KST])(sm + AR * KST);
    float (*Ps)[64]  = (float(*)[64])(sm + 2 * AR * KST);

    const int s0 = blockIdx.x * 32;
    const int h  = blockIdx.y;
    const int b  = blockIdx.z;
    const int tid = threadIdx.x;
    const int base = (b * SEQ) * HS + h * HD;

    for (int i = tid; i < AR * 16; i += 1024) {
        int r = i >> 4, c4 = (i & 15) * 4;
        int j = s0 - HALF + r;
        float4 kv = make_float4(0.f, 0.f, 0.f, 0.f), vv = kv;
        if (j >= 0 && j < SEQ) {
            int off = base + j * HS + c4;
            kv = *(const float4*)&g_k[off];
            vv = *(const float4*)&g_v[off];
        }
        *(float4*)&Ks[r][c4] = kv;
        *(float4*)&Vs[r][c4] = vv;
    }
    __syncthreads();

    const int wq   = tid >> 5;
    const int lane = tid & 31;
    const float* qrow = g_q + base + (s0 + wq) * HS;

    float sc0 = 0.f, sc1 = 0.f;
    #pragma unroll
    for (int d4 = 0; d4 < 16; d4++) {
        float4 q  = __ldg((const float4*)(qrow + d4 * 4));
        float4 k0 = *(const float4*)&Ks[wq + lane][d4 * 4];
        float4 k1 = *(const float4*)&Ks[wq + lane + 32][d4 * 4];
        sc0 += q.x * k0.x + q.y * k0.y + q.z * k0.z + q.w * k0.w;
        sc1 += q.x * k1.x + q.y * k1.y + q.z * k1.z + q.w * k1.w;
    }
    sc0 *= 0.125f;
    sc1 *= 0.125f;

    float m = fmaxf(sc0, sc1);
    #pragma unroll
    for (int o = 16; o; o >>= 1) m = fmaxf(m, __shfl_xor_sync(0xFFFFFFFFu, m, o));
    float e0 = __expf(sc0 - m);
    float e1 = __expf(sc1 - m);
    float sum = e0 + e1;
    #pragma unroll
    for (int o = 16; o; o >>= 1) sum += __shfl_xor_sync(0xFFFFFFFFu, sum, o);
    float inv = 1.f / sum;
    Ps[wq][lane]      = e0 * inv;
    Ps[wq][lane + 32] = e1 * inv;
    __syncwarp();

    float c0 = 0.f, c1 = 0.f;
    #pragma unroll
    for (int w = 0; w < 64; w++) {
        float p = Ps[wq][w];
        float2 v = *(const float2*)&Vs[wq + w][2 * lane];
        c0 += p * v.x;
        c1 += p * v.y;
    }
    const int orow = base + (s0 + wq) * HS + 2 * lane;
    __nv_bfloat162 hi2, lo2;
    hi2.x = __float2bfloat16(c0);
    hi2.y = __float2bfloat16(c1);
    lo2.x = __float2bfloat16(c0 - __bfloat162float(hi2.x));
    lo2.y = __float2bfloat16(c1 - __bfloat162float(hi2.y));
    *(__nv_bfloat162*)&g_chi[orow] = hi2;
    *(__nv_bfloat162*)&g_clo[orow] = lo2;
}

// ---------------------------------------------------------------------------
extern "C" void kernel_launch(void* const* d_in, const int* in_sizes, int n_in,
                              void* d_out, int out_size)
{
    const float* X  = (const float*)d_in[0];
    const float* Wq = (const float*)d_in[1];
    const float* bq = (const float*)d_in[2];
    const float* Wk = (const float*)d_in[3];
    const float* bk = (const float*)d_in[4];
    const float* Wv = (const float*)d_in[5];
    const float* bv = (const float*)d_in[6];
    const float* Wo = (const float*)d_in[7];
    const float* bo = (const float*)d_in[8];
    float* out = (float*)d_out;

    static bool attr_done = false;
    if (!attr_done) {
        cudaFuncSetAttribute(qkv_kernel,  cudaFuncAttributeMaxDynamicSharedMemorySize, SMEM_GEMM);
        cudaFuncSetAttribute(out_kernel,  cudaFuncAttributeMaxDynamicSharedMemorySize, SMEM_GEMM);
        cudaFuncSetAttribute(attn_kernel, cudaFuncAttributeMaxDynamicSharedMemorySize, SMEM_ATTN);
        attr_done = true;
    }

    split_kernel<<<1024, 256>>>(X, Wq, Wk, Wv, Wo);

    dim3 qkv_grid(HS / BN, MTOK / BM, 3);      // (6, 16, 3) = 288
    qkv_kernel<<<qkv_grid, 256, SMEM_GEMM>>>(bq, bk, bv);

    dim3 attn_grid(SEQ / 32, NH, BATCH);       // (32, 12, 2)
    attn_kernel<<<attn_grid, 1024, SMEM_ATTN>>>();

    dim3 out_grid(HS / BN, MTOK / BM, 1);      // (6, 16) = 96
    out_kernel<<<out_grid, 256, SMEM_GEMM>>>(bo, out);
}

// round 8
// speedup vs baseline: 1.5465x; 1.0652x over previous
#include <cuda_runtime.h>
#include <cuda_bf16.h>
#include <cstdint>

#define BATCH 2
#define SEQ   1024
#define HS    768
#define NH    12
#define HD    64
#define WIN   64
#define HALF  32
#define MTOK  (BATCH*SEQ)   // 2048
#define NX    (MTOK*HS)
#define NW    (HS*HS)

#define BM 64
#define BN 128
#define BK 32
#define NKC (HS / BK)       // 24

// ---------------------------------------------------------------------------
// Device-global scratch
// ---------------------------------------------------------------------------
__device__ float g_q[NX];
__device__ float g_k[NX];
__device__ float g_v[NX];
__device__ __nv_bfloat16 g_xhi[NX], g_xlo[NX];
__device__ __nv_bfloat16 g_chi[NX], g_clo[NX];
__device__ __nv_bfloat16 g_wqhi[NW], g_wqlo[NW];
__device__ __nv_bfloat16 g_wkhi[NW], g_wklo[NW];
__device__ __nv_bfloat16 g_wvhi[NW], g_wvlo[NW];
__device__ __nv_bfloat16 g_wohi[NW], g_wolo[NW];

// ---------------------------------------------------------------------------
// PTX helpers
// ---------------------------------------------------------------------------
__device__ __forceinline__ uint32_t smem_u32(const void* p) {
    uint32_t a;
    asm("{ .reg .u64 t; cvta.to.shared.u64 t, %1; cvt.u32.u64 %0, t; }" : "=r"(a) : "l"(p));
    return a;
}
__device__ __forceinline__ void cp16(uint32_t dst, const void* src) {
    asm volatile("cp.async.cg.shared.global [%0], [%1], 16;" :: "r"(dst), "l"(src));
}
#define CP_COMMIT() asm volatile("cp.async.commit_group;")
#define CP_WAIT1()  asm volatile("cp.async.wait_group 1;")

__device__ __forceinline__ void ldsm4(uint32_t* r, uint32_t addr) {
    asm volatile("ldmatrix.sync.aligned.m8n8.x4.shared.b16 {%0,%1,%2,%3}, [%4];"
        : "=r"(r[0]), "=r"(r[1]), "=r"(r[2]), "=r"(r[3]) : "r"(addr));
}
__device__ __forceinline__ void mma_bf16(float* d, const uint32_t* a, uint32_t b0, uint32_t b1) {
    asm volatile(
        "mma.sync.aligned.m16n8k16.row.col.f32.bf16.bf16.f32 "
        "{%0,%1,%2,%3}, {%4,%5,%6,%7}, {%8,%9}, {%0,%1,%2,%3};"
        : "+f"(d[0]), "+f"(d[1]), "+f"(d[2]), "+f"(d[3])
        : "r"(a[0]), "r"(a[1]), "r"(a[2]), "r"(a[3]), "r"(b0), "r"(b1));
}

// ---------------------------------------------------------------------------
// smem per stage: Ahi(64 rows), Alo(64), Bhi(128), Blo(128); row = 32 bf16 =
// 64B padded to 80B (conflict-free ldmatrix).  Stage = 384*80 = 30720 B.
//   Ahi @ 0, Alo @ 5120, Bhi @ 10240, Blo @ 20480.
// ---------------------------------------------------------------------------
#define STAGE_B  30720
#define SMEM_GEMM (3 * STAGE_B)

__device__ __forceinline__ void load_chunk(
    uint32_t sb, int st, int kc,
    const __nv_bfloat16* __restrict__ Ahi, const __nv_bfloat16* __restrict__ Alo,
    const __nv_bfloat16* __restrict__ Bhi, const __nv_bfloat16* __restrict__ Blo,
    int by, int bx, int tid)
{
    const int k0 = kc * BK;
    const uint32_t base = sb + (uint32_t)st * STAGE_B;
    #pragma unroll
    for (int it = 0; it < 6; it++) {
        int idx = it * 256 + tid;          // 0..1535
        int r   = idx >> 2;                // 0..383
        int cb  = idx & 3;                 // 16B chunk in 64B row
        const __nv_bfloat16* src; uint32_t toff; int row;
        if (r < 64)       { src = Ahi + (size_t)(by * BM + r) * HS;         toff = 0;     row = r; }
        else if (r < 128) { src = Alo + (size_t)(by * BM + (r - 64)) * HS;  toff = 5120;  row = r - 64; }
        else if (r < 256) { src = Bhi + (size_t)(bx * BN + (r - 128)) * HS; toff = 10240; row = r - 128; }
        else              { src = Blo + (size_t)(bx * BN + (r - 256)) * HS; toff = 20480; row = r - 256; }
        cp16(base + toff + (uint32_t)row * 80 + (uint32_t)cb * 16, src + k0 + cb * 8);
    }
}

// ---------------------------------------------------------------------------
// bf16x3 HMMA GEMM: C[M,N] = (Ahi+Alo)[M,K] @ (Bhi+Blo)[N,K]^T + bias
// CTA 64x128, 8 warps (2M x 4N), warp tile 32x32, 2 CTAs/SM.
// 3-stage cp.async pipeline, one __syncthreads per k-iter.
// ---------------------------------------------------------------------------
__device__ __forceinline__ void hgemm(
    const __nv_bfloat16* __restrict__ Ahi, const __nv_bfloat16* __restrict__ Alo,
    const __nv_bfloat16* __restrict__ Bhi, const __nv_bfloat16* __restrict__ Blo,
    const float* __restrict__ bias, float* __restrict__ C,
    int bx, int by)
{
    extern __shared__ char smem[];
    const uint32_t sb = smem_u32(smem);
    const int tid  = threadIdx.x;
    const int lane = tid & 31;
    const int warp = tid >> 5;
    const int wm   = warp & 1;          // 0..1 -> M*32
    const int wn   = warp >> 1;         // 0..3 -> N*32

    float acc[2][4][4];
    #pragma unroll
    for (int i = 0; i < 2; i++)
        #pragma unroll
        for (int j = 0; j < 4; j++)
            #pragma unroll
            for (int r = 0; r < 4; r++) acc[i][j][r] = 0.f;

    load_chunk(sb, 0, 0, Ahi, Alo, Bhi, Blo, by, bx, tid); CP_COMMIT();
    load_chunk(sb, 1, 1, Ahi, Alo, Bhi, Blo, by, bx, tid); CP_COMMIT();

    const uint32_t arow = (uint32_t)(lane & 15);
    const uint32_t asel = (uint32_t)(lane >> 4) * 16;

    for (int kc = 0; kc < NKC; kc++) {
        CP_WAIT1();
        __syncthreads();
        if (kc + 2 < NKC) {
            load_chunk(sb, (kc + 2) % 3, kc + 2, Ahi, Alo, Bhi, Blo, by, bx, tid);
            CP_COMMIT();
        }
        const uint32_t base = sb + (uint32_t)(kc % 3) * STAGE_B;

        #pragma unroll
        for (int ks = 0; ks < 2; ks++) {
            const uint32_t colb = (uint32_t)ks * 32 + asel;
            uint32_t ah[2][4], al[2][4], bh[2][4], bl[2][4];
            #pragma unroll
            for (int i = 0; i < 2; i++) {
                uint32_t ro = (uint32_t)(wm * 32 + i * 16) + arow;
                ldsm4(ah[i], base +         ro * 80 + colb);
                ldsm4(al[i], base + 5120  + ro * 80 + colb);
            }
            #pragma unroll
            for (int jj = 0; jj < 2; jj++) {
                uint32_t ro = (uint32_t)(wn * 32 + jj * 16) + arow;
                ldsm4(bh[jj], base + 10240 + ro * 80 + colb);
                ldsm4(bl[jj], base + 20480 + ro * 80 + colb);
            }
            // pass 1: hi*hi
            #pragma unroll
            for (int i = 0; i < 2; i++)
                #pragma unroll
                for (int jj = 0; jj < 2; jj++) {
                    mma_bf16(acc[i][jj * 2 + 0], ah[i], bh[jj][0], bh[jj][2]);
                    mma_bf16(acc[i][jj * 2 + 1], ah[i], bh[jj][1], bh[jj][3]);
                }
            // pass 2: hi*lo
            #pragma unroll
            for (int i = 0; i < 2; i++)
                #pragma unroll
                for (int jj = 0; jj < 2; jj++) {
                    mma_bf16(acc[i][jj * 2 + 0], ah[i], bl[jj][0], bl[jj][2]);
                    mma_bf16(acc[i][jj * 2 + 1], ah[i], bl[jj][1], bl[jj][3]);
                }
            // pass 3: lo*hi
            #pragma unroll
            for (int i = 0; i < 2; i++)
                #pragma unroll
                for (int jj = 0; jj < 2; jj++) {
                    mma_bf16(acc[i][jj * 2 + 0], al[i], bh[jj][0], bh[jj][2]);
                    mma_bf16(acc[i][jj * 2 + 1], al[i], bh[jj][1], bh[jj][3]);
                }
        }
        __syncthreads();
    }

    const int g  = lane >> 2;
    const int tg = lane & 3;
    #pragma unroll
    for (int i = 0; i < 2; i++) {
        const int row = by * BM + wm * 32 + i * 16 + g;
        #pragma unroll
        for (int j = 0; j < 4; j++) {
            const int col = bx * BN + wn * 32 + j * 8 + tg * 2;
            const float b0 = bias[col], b1 = bias[col + 1];
            *(float2*)&C[(size_t)row * HS + col] =
                make_float2(acc[i][j][0] + b0, acc[i][j][1] + b1);
            *(float2*)&C[(size_t)(row + 8) * HS + col] =
                make_float2(acc[i][j][2] + b0, acc[i][j][3] + b1);
        }
    }
}

__global__ __launch_bounds__(256, 2) void qkv_kernel(
    const float* __restrict__ bq, const float* __restrict__ bk, const float* __restrict__ bv)
{
    const __nv_bfloat16 *Bh, *Bl; const float* b; float* C;
    if (blockIdx.z == 0)      { Bh = g_wqhi; Bl = g_wqlo; b = bq; C = g_q; }
    else if (blockIdx.z == 1) { Bh = g_wkhi; Bl = g_wklo; b = bk; C = g_k; }
    else                      { Bh = g_wvhi; Bl = g_wvlo; b = bv; C = g_v; }
    hgemm(g_xhi, g_xlo, Bh, Bl, b, C, blockIdx.x, blockIdx.y);
}

__global__ __launch_bounds__(256, 2) void out_kernel(
    const float* __restrict__ bo, float* __restrict__ out)
{
    hgemm(g_chi, g_clo, g_wohi, g_wolo, bo, out, blockIdx.x, blockIdx.y);
}

// ---------------------------------------------------------------------------
// Split fp32 -> bf16 hi/lo (X + 4 weights).
// ---------------------------------------------------------------------------
__global__ void split_kernel(
    const float* __restrict__ X,
    const float* __restrict__ Wq, const float* __restrict__ Wk,
    const float* __restrict__ Wv, const float* __restrict__ Wo)
{
    const int tot4 = (NX + 4 * NW) / 4;
    for (int i4 = blockIdx.x * blockDim.x + threadIdx.x; i4 < tot4; i4 += gridDim.x * blockDim.x) {
        int i = i4 * 4;
        const float* src; __nv_bfloat16 *hi, *lo; int r;
        if (i < NX) { src = X; hi = g_xhi; lo = g_xlo; r = i; }
        else {
            int j = i - NX; int w = j / NW; r = j - w * NW;
            if (w == 0)      { src = Wq; hi = g_wqhi; lo = g_wqlo; }
            else if (w == 1) { src = Wk; hi = g_wkhi; lo = g_wklo; }
            else if (w == 2) { src = Wv; hi = g_wvhi; lo = g_wvlo; }
            else             { src = Wo; hi = g_wohi; lo = g_wolo; }
        }
        float4 x = *(const float4*)(src + r);
        float xs[4] = {x.x, x.y, x.z, x.w};
        __nv_bfloat162 h2[2], l2[2];
        #pragma unroll
        for (int t = 0; t < 4; t++) {
            __nv_bfloat16 h = __float2bfloat16(xs[t]);
            ((__nv_bfloat16*)h2)[t] = h;
            ((__nv_bfloat16*)l2)[t] = __float2bfloat16(xs[t] - __bfloat162float(h));
        }
        *(__nv_bfloat162*)(hi + r)     = h2[0];
        *(__nv_bfloat162*)(hi + r + 2) = h2[1];
        *(__nv_bfloat162*)(lo + r)     = l2[0];
        *(__nv_bfloat162*)(lo + r + 2) = l2[1];
    }
}

// ---------------------------------------------------------------------------
// Sliding-window attention (proven R4 version).
// ---------------------------------------------------------------------------
#define AR 95
#define KST 68
#define SMEM_ATTN ((2*AR*KST + 32*64) * 4)

__global__ __launch_bounds__(1024) void attn_kernel()
{
    extern __shared__ float sm[];
    float (*Ks)[KST] = (float(*)[KST])sm;
    float (*Vs)[KST] = (float(*)[KST])(sm + AR * KST);
    float (*Ps)[64]  = (float(*)[64])(sm + 2 * AR * KST);

    const int s0 = blockIdx.x * 32;
    const int h  = blockIdx.y;
    const int b  = blockIdx.z;
    const int tid = threadIdx.x;
    const int base = (b * SEQ) * HS + h * HD;

    for (int i = tid; i < AR * 16; i += 1024) {
        int r = i >> 4, c4 = (i & 15) * 4;
        int j = s0 - HALF + r;
        float4 kv = make_float4(0.f, 0.f, 0.f, 0.f), vv = kv;
        if (j >= 0 && j < SEQ) {
            int off = base + j * HS + c4;
            kv = *(const float4*)&g_k[off];
            vv = *(const float4*)&g_v[off];
        }
        *(float4*)&Ks[r][c4] = kv;
        *(float4*)&Vs[r][c4] = vv;
    }
    __syncthreads();

    const int wq   = tid >> 5;
    const int lane = tid & 31;
    const float* qrow = g_q + base + (s0 + wq) * HS;

    float sc0 = 0.f, sc1 = 0.f;
    #pragma unroll
    for (int d4 = 0; d4 < 16; d4++) {
        float4 q  = __ldg((const float4*)(qrow + d4 * 4));
        float4 k0 = *(const float4*)&Ks[wq + lane][d4 * 4];
        float4 k1 = *(const float4*)&Ks[wq + lane + 32][d4 * 4];
        sc0 += q.x * k0.x + q.y * k0.y + q.z * k0.z + q.w * k0.w;
        sc1 += q.x * k1.x + q.y * k1.y + q.z * k1.z + q.w * k1.w;
    }
    sc0 *= 0.125f;
    sc1 *= 0.125f;

    float m = fmaxf(sc0, sc1);
    #pragma unroll
    for (int o = 16; o; o >>= 1) m = fmaxf(m, __shfl_xor_sync(0xFFFFFFFFu, m, o));
    float e0 = __expf(sc0 - m);
    float e1 = __expf(sc1 - m);
    float sum = e0 + e1;
    #pragma unroll
    for (int o = 16; o; o >>= 1) sum += __shfl_xor_sync(0xFFFFFFFFu, sum, o);
    float inv = 1.f / sum;
    Ps[wq][lane]      = e0 * inv;
    Ps[wq][lane + 32] = e1 * inv;
    __syncwarp();

    float c0 = 0.f, c1 = 0.f;
    #pragma unroll
    for (int w = 0; w < 64; w++) {
        float p = Ps[wq][w];
        float2 v = *(const float2*)&Vs[wq + w][2 * lane];
        c0 += p * v.x;
        c1 += p * v.y;
    }
    const int orow = base + (s0 + wq) * HS + 2 * lane;
    __nv_bfloat162 hi2, lo2;
    hi2.x = __float2bfloat16(c0);
    hi2.y = __float2bfloat16(c1);
    lo2.x = __float2bfloat16(c0 - __bfloat162float(hi2.x));
    lo2.y = __float2bfloat16(c1 - __bfloat162float(hi2.y));
    *(__nv_bfloat162*)&g_chi[orow] = hi2;
    *(__nv_bfloat162*)&g_clo[orow] = lo2;
}

// ---------------------------------------------------------------------------
extern "C" void kernel_launch(void* const* d_in, const int* in_sizes, int n_in,
                              void* d_out, int out_size)
{
    const float* X  = (const float*)d_in[0];
    const float* Wq = (const float*)d_in[1];
    const float* bq = (const float*)d_in[2];
    const float* Wk = (const float*)d_in[3];
    const float* bk = (const float*)d_in[4];
    const float* Wv = (const float*)d_in[5];
    const float* bv = (const float*)d_in[6];
    const float* Wo = (const float*)d_in[7];
    const float* bo = (const float*)d_in[8];
    float* out = (float*)d_out;

    static bool attr_done = false;
    if (!attr_done) {
        cudaFuncSetAttribute(qkv_kernel,  cudaFuncAttributeMaxDynamicSharedMemorySize, SMEM_GEMM);
        cudaFuncSetAttribute(out_kernel,  cudaFuncAttributeMaxDynamicSharedMemorySize, SMEM_GEMM);
        cudaFuncSetAttribute(attn_kernel, cudaFuncAttributeMaxDynamicSharedMemorySize, SMEM_ATTN);
        attr_done = true;
    }

    split_kernel<<<1024, 256>>>(X, Wq, Wk, Wv, Wo);

    dim3 qkv_grid(HS / BN, MTOK / BM, 3);      // (6, 32, 3) = 576
    qkv_kernel<<<qkv_grid, 256, SMEM_GEMM>>>(bq, bk, bv);

    dim3 attn_grid(SEQ / 32, NH, BATCH);       // (32, 12, 2)
    attn_kernel<<<attn_grid, 1024, SMEM_ATTN>>>();

    dim3 out_grid(HS / BN, MTOK / BM, 1);      // (6, 32) = 192
    out_kernel<<<out_grid, 256, SMEM_GEMM>>>(bo, out);
}

// round 9
// speedup vs baseline: 1.7256x; 1.1159x over previous
#include <cuda_runtime.h>
#include <cuda_bf16.h>
#include <cstdint>

#define BATCH 2
#define SEQ   1024
#define HS    768
#define NH    12
#define HD    64
#define WIN   64
#define HALF  32
#define MTOK  (BATCH*SEQ)   // 2048
#define NX    (MTOK*HS)
#define NW    (HS*HS)
#define BK    32
#define NKC   (HS / BK)     // 24

// ---------------------------------------------------------------------------
// Device-global scratch
// ---------------------------------------------------------------------------
__device__ float g_q[NX];
__device__ float g_k[NX];
__device__ float g_v[NX];
__device__ __nv_bfloat16 g_xhi[NX], g_xlo[NX];
__device__ __nv_bfloat16 g_chi[NX], g_clo[NX];
__device__ __nv_bfloat16 g_wqhi[NW], g_wqlo[NW];
__device__ __nv_bfloat16 g_wkhi[NW], g_wklo[NW];
__device__ __nv_bfloat16 g_wvhi[NW], g_wvlo[NW];
__device__ __nv_bfloat16 g_wohi[NW], g_wolo[NW];

// ---------------------------------------------------------------------------
// PTX helpers
// ---------------------------------------------------------------------------
__device__ __forceinline__ uint32_t smem_u32(const void* p) {
    uint32_t a;
    asm("{ .reg .u64 t; cvta.to.shared.u64 t, %1; cvt.u32.u64 %0, t; }" : "=r"(a) : "l"(p));
    return a;
}
__device__ __forceinline__ void cp16(uint32_t dst, const void* src) {
    asm volatile("cp.async.cg.shared.global [%0], [%1], 16;" :: "r"(dst), "l"(src));
}
#define CP_COMMIT() asm volatile("cp.async.commit_group;")
#define CP_WAIT1()  asm volatile("cp.async.wait_group 1;")

__device__ __forceinline__ void ldsm4(uint32_t* r, uint32_t addr) {
    asm volatile("ldmatrix.sync.aligned.m8n8.x4.shared.b16 {%0,%1,%2,%3}, [%4];"
        : "=r"(r[0]), "=r"(r[1]), "=r"(r[2]), "=r"(r[3]) : "r"(addr));
}
__device__ __forceinline__ void mma_bf16(float* d, const uint32_t* a, uint32_t b0, uint32_t b1) {
    asm volatile(
        "mma.sync.aligned.m16n8k16.row.col.f32.bf16.bf16.f32 "
        "{%0,%1,%2,%3}, {%4,%5,%6,%7}, {%8,%9}, {%0,%1,%2,%3};"
        : "+f"(d[0]), "+f"(d[1]), "+f"(d[2]), "+f"(d[3])
        : "r"(a[0]), "r"(a[1]), "r"(a[2]), "r"(a[3]), "r"(b0), "r"(b1));
}

// ===========================================================================
// QKV GEMM: CTA 128x256, 8 warps (2M x 4N), warp tile 64x64, 1 CTA/SM.
// smem/stage: Ahi(128r) Alo(128r) Bhi(256r) Blo(256r), row 64B padded 80B.
//   Ahi@0  Alo@10240  Bhi@20480  Blo@40960   stage = 61440 B, 3 stages.
// ===========================================================================
#define QSTG  61440
#define SMEM_QKV (3 * QSTG)

__device__ __forceinline__ void load_q(
    uint32_t sb, int st, int kc,
    const __nv_bfloat16* __restrict__ Ahi, const __nv_bfloat16* __restrict__ Alo,
    const __nv_bfloat16* __restrict__ Bhi, const __nv_bfloat16* __restrict__ Blo,
    int by, int bx, int tid)
{
    const int k0 = kc * BK;
    const uint32_t base = sb + (uint32_t)st * QSTG;
    #pragma unroll
    for (int it = 0; it < 12; it++) {
        int idx = it * 256 + tid;          // 0..3071
        int r   = idx >> 2;                // 0..767
        int cb  = idx & 3;
        const __nv_bfloat16* src; uint32_t toff; int row;
        if (r < 128)      { src = Ahi + (size_t)(by * 128 + r) * HS;         toff = 0;     row = r; }
        else if (r < 256) { src = Alo + (size_t)(by * 128 + (r - 128)) * HS; toff = 10240; row = r - 128; }
        else if (r < 512) { src = Bhi + (size_t)(bx * 256 + (r - 256)) * HS; toff = 20480; row = r - 256; }
        else              { src = Blo + (size_t)(bx * 256 + (r - 512)) * HS; toff = 40960; row = r - 512; }
        cp16(base + toff + (uint32_t)row * 80 + (uint32_t)cb * 16, src + k0 + cb * 8);
    }
}

__global__ __launch_bounds__(256, 1) void qkv_kernel(
    const float* __restrict__ bq, const float* __restrict__ bk, const float* __restrict__ bv)
{
    const __nv_bfloat16 *Bh, *Bl; const float* bias; float* C;
    if (blockIdx.z == 0)      { Bh = g_wqhi; Bl = g_wqlo; bias = bq; C = g_q; }
    else if (blockIdx.z == 1) { Bh = g_wkhi; Bl = g_wklo; bias = bk; C = g_k; }
    else                      { Bh = g_wvhi; Bl = g_wvlo; bias = bv; C = g_v; }

    extern __shared__ char smem[];
    const uint32_t sb = smem_u32(smem);
    const int tid  = threadIdx.x;
    const int lane = tid & 31;
    const int warp = tid >> 5;
    const int wm   = warp & 1;          // 0..1 -> M*64
    const int wn   = warp >> 1;         // 0..3 -> N*64
    const int bx = blockIdx.x, by = blockIdx.y;

    float acc[4][8][4];
    #pragma unroll
    for (int i = 0; i < 4; i++)
        #pragma unroll
        for (int j = 0; j < 8; j++)
            #pragma unroll
            for (int r = 0; r < 4; r++) acc[i][j][r] = 0.f;

    load_q(sb, 0, 0, g_xhi, g_xlo, Bh, Bl, by, bx, tid); CP_COMMIT();
    load_q(sb, 1, 1, g_xhi, g_xlo, Bh, Bl, by, bx, tid); CP_COMMIT();

    const uint32_t arow = (uint32_t)(lane & 15);
    const uint32_t asel = (uint32_t)(lane >> 4) * 16;

    for (int kc = 0; kc < NKC; kc++) {
        CP_WAIT1();
        __syncthreads();
        if (kc + 2 < NKC) {
            load_q(sb, (kc + 2) % 3, kc + 2, g_xhi, g_xlo, Bh, Bl, by, bx, tid);
            CP_COMMIT();
        }
        const uint32_t base = sb + (uint32_t)(kc % 3) * QSTG;

        #pragma unroll
        for (int ks = 0; ks < 2; ks++) {
            const uint32_t colb = (uint32_t)ks * 32 + asel;
            uint32_t ah[4][4], al[4][4];
            #pragma unroll
            for (int i = 0; i < 4; i++) {
                uint32_t ro = (uint32_t)(wm * 64 + i * 16) + arow;
                ldsm4(ah[i], base +         ro * 80 + colb);
                ldsm4(al[i], base + 10240 + ro * 80 + colb);
            }
            #pragma unroll
            for (int jj = 0; jj < 4; jj++) {
                uint32_t bh[4], bl[4];
                uint32_t ro = (uint32_t)(wn * 64 + jj * 16) + arow;
                ldsm4(bh, base + 20480 + ro * 80 + colb);
                ldsm4(bl, base + 40960 + ro * 80 + colb);
                #pragma unroll
                for (int i = 0; i < 4; i++) {            // hi*hi
                    mma_bf16(acc[i][jj * 2 + 0], ah[i], bh[0], bh[2]);
                    mma_bf16(acc[i][jj * 2 + 1], ah[i], bh[1], bh[3]);
                }
                #pragma unroll
                for (int i = 0; i < 4; i++) {            // hi*lo
                    mma_bf16(acc[i][jj * 2 + 0], ah[i], bl[0], bl[2]);
                    mma_bf16(acc[i][jj * 2 + 1], ah[i], bl[1], bl[3]);
                }
                #pragma unroll
                for (int i = 0; i < 4; i++) {            // lo*hi
                    mma_bf16(acc[i][jj * 2 + 0], al[i], bh[0], bh[2]);
                    mma_bf16(acc[i][jj * 2 + 1], al[i], bh[1], bh[3]);
                }
            }
        }
        __syncthreads();
    }

    const int g  = lane >> 2;
    const int tg = lane & 3;
    #pragma unroll
    for (int i = 0; i < 4; i++) {
        const int row = by * 128 + wm * 64 + i * 16 + g;
        #pragma unroll
        for (int jj = 0; jj < 4; jj++) {
            #pragma unroll
            for (int s = 0; s < 2; s++) {
                const int col = bx * 256 + wn * 64 + jj * 16 + s * 8 + tg * 2;
                const float* a = acc[i][jj * 2 + s];
                const float b0 = bias[col], b1 = bias[col + 1];
                *(float2*)&C[(size_t)row * HS + col]       = make_float2(a[0] + b0, a[1] + b1);
                *(float2*)&C[(size_t)(row + 8) * HS + col] = make_float2(a[2] + b0, a[3] + b1);
            }
        }
    }
}

// ===========================================================================
// Output projection: CTA 64x96, 6 warps (2M x 3N), warp tile 32x32, 3 CTA/SM.
// smem/stage: Ahi(64) Alo(64) Bhi(96) Blo(96) rows * 80B = 25600 B, 3 stages.
//   Ahi@0  Alo@5120  Bhi@10240  Blo@17920
// ===========================================================================
#define OSTG  25600
#define SMEM_OUT (3 * OSTG)

__device__ __forceinline__ void load_o(
    uint32_t sb, int st, int kc, int by, int bx, int tid)
{
    const int k0 = kc * BK;
    const uint32_t base = sb + (uint32_t)st * OSTG;
    #pragma unroll
    for (int it = 0; it < 7; it++) {
        int idx = it * 192 + tid;          // 0..1343, valid < 1280
        if (idx < 1280) {
            int r  = idx >> 2;             // 0..319
            int cb = idx & 3;
            const __nv_bfloat16* src; uint32_t toff; int row;
            if (r < 64)       { src = g_chi  + (size_t)(by * 64 + r) * HS;        toff = 0;     row = r; }
            else if (r < 128) { src = g_clo  + (size_t)(by * 64 + (r - 64)) * HS; toff = 5120;  row = r - 64; }
            else if (r < 224) { src = g_wohi + (size_t)(bx * 96 + (r - 128)) * HS; toff = 10240; row = r - 128; }
            else              { src = g_wolo + (size_t)(bx * 96 + (r - 224)) * HS; toff = 17920; row = r - 224; }
            cp16(base + toff + (uint32_t)row * 80 + (uint32_t)cb * 16, src + k0 + cb * 8);
        }
    }
}

__global__ __launch_bounds__(192, 3) void out_kernel(
    const float* __restrict__ bo, float* __restrict__ Cout)
{
    extern __shared__ char smem[];
    const uint32_t sb = smem_u32(smem);
    const int tid  = threadIdx.x;
    const int lane = tid & 31;
    const int warp = tid >> 5;
    const int wm   = warp & 1;          // 0..1 -> M*32
    const int wn   = warp >> 1;         // 0..2 -> N*32
    const int bx = blockIdx.x, by = blockIdx.y;

    float acc[2][4][4];
    #pragma unroll
    for (int i = 0; i < 2; i++)
        #pragma unroll
        for (int j = 0; j < 4; j++)
            #pragma unroll
            for (int r = 0; r < 4; r++) acc[i][j][r] = 0.f;

    load_o(sb, 0, 0, by, bx, tid); CP_COMMIT();
    load_o(sb, 1, 1, by, bx, tid); CP_COMMIT();

    const uint32_t arow = (uint32_t)(lane & 15);
    const uint32_t asel = (uint32_t)(lane >> 4) * 16;

    for (int kc = 0; kc < NKC; kc++) {
        CP_WAIT1();
        __syncthreads();
        if (kc + 2 < NKC) {
            load_o(sb, (kc + 2) % 3, kc + 2, by, bx, tid);
            CP_COMMIT();
        }
        const uint32_t base = sb + (uint32_t)(kc % 3) * OSTG;

        #pragma unroll
        for (int ks = 0; ks < 2; ks++) {
            const uint32_t colb = (uint32_t)ks * 32 + asel;
            uint32_t ah[2][4], al[2][4];
            #pragma unroll
            for (int i = 0; i < 2; i++) {
                uint32_t ro = (uint32_t)(wm * 32 + i * 16) + arow;
                ldsm4(ah[i], base +        ro * 80 + colb);
                ldsm4(al[i], base + 5120 + ro * 80 + colb);
            }
            #pragma unroll
            for (int jj = 0; jj < 2; jj++) {
                uint32_t bh[4], bl[4];
                uint32_t ro = (uint32_t)(wn * 32 + jj * 16) + arow;
                ldsm4(bh, base + 10240 + ro * 80 + colb);
                ldsm4(bl, base + 17920 + ro * 80 + colb);
                #pragma unroll
                for (int i = 0; i < 2; i++) {
                    mma_bf16(acc[i][jj * 2 + 0], ah[i], bh[0], bh[2]);
                    mma_bf16(acc[i][jj * 2 + 1], ah[i], bh[1], bh[3]);
                }
                #pragma unroll
                for (int i = 0; i < 2; i++) {
                    mma_bf16(acc[i][jj * 2 + 0], ah[i], bl[0], bl[2]);
                    mma_bf16(acc[i][jj * 2 + 1], ah[i], bl[1], bl[3]);
                }
                #pragma unroll
                for (int i = 0; i < 2; i++) {
                    mma_bf16(acc[i][jj * 2 + 0], al[i], bh[0], bh[2]);
                    mma_bf16(acc[i][jj * 2 + 1], al[i], bh[1], bh[3]);
                }
            }
        }
        __syncthreads();
    }

    const int g  = lane >> 2;
    const int tg = lane & 3;
    #pragma unroll
    for (int i = 0; i < 2; i++) {
        const int row = by * 64 + wm * 32 + i * 16 + g;
        #pragma unroll
        for (int j = 0; j < 4; j++) {
            const int col = bx * 96 + wn * 32 + (j >> 1) * 16 + (j & 1) * 8 + tg * 2;
            const float b0 = bo[col], b1 = bo[col + 1];
            *(float2*)&Cout[(size_t)row * HS + col] =
                make_float2(acc[i][j][0] + b0, acc[i][j][1] + b1);
            *(float2*)&Cout[(size_t)(row + 8) * HS + col] =
                make_float2(acc[i][j][2] + b0, acc[i][j][3] + b1);
        }
    }
}

// ---------------------------------------------------------------------------
// Split fp32 -> bf16 hi/lo (X + 4 weights).
// ---------------------------------------------------------------------------
__global__ void split_kernel(
    const float* __restrict__ X,
    const float* __restrict__ Wq, const float* __restrict__ Wk,
    const float* __restrict__ Wv, const float* __restrict__ Wo)
{
    const int tot4 = (NX + 4 * NW) / 4;
    for (int i4 = blockIdx.x * blockDim.x + threadIdx.x; i4 < tot4; i4 += gridDim.x * blockDim.x) {
        int i = i4 * 4;
        const float* src; __nv_bfloat16 *hi, *lo; int r;
        if (i < NX) { src = X; hi = g_xhi; lo = g_xlo; r = i; }
        else {
            int j = i - NX; int w = j / NW; r = j - w * NW;
            if (w == 0)      { src = Wq; hi = g_wqhi; lo = g_wqlo; }
            else if (w == 1) { src = Wk; hi = g_wkhi; lo = g_wklo; }
            else if (w == 2) { src = Wv; hi = g_wvhi; lo = g_wvlo; }
            else             { src = Wo; hi = g_wohi; lo = g_wolo; }
        }
        float4 x = *(const float4*)(src + r);
        float xs[4] = {x.x, x.y, x.z, x.w};
        __nv_bfloat162 h2[2], l2[2];
        #pragma unroll
        for (int t = 0; t < 4; t++) {
            __nv_bfloat16 h = __float2bfloat16(xs[t]);
            ((__nv_bfloat16*)h2)[t] = h;
            ((__nv_bfloat16*)l2)[t] = __float2bfloat16(xs[t] - __bfloat162float(h));
        }
        *(__nv_bfloat162*)(hi + r)     = h2[0];
        *(__nv_bfloat162*)(hi + r + 2) = h2[1];
        *(__nv_bfloat162*)(lo + r)     = l2[0];
        *(__nv_bfloat162*)(lo + r + 2) = l2[1];
    }
}

// ---------------------------------------------------------------------------
// Sliding-window attention (proven version).
// ---------------------------------------------------------------------------
#define AR 95
#define KST 68
#define SMEM_ATTN ((2*AR*KST + 32*64) * 4)

__global__ __launch_bounds__(1024) void attn_kernel()
{
    extern __shared__ float sm[];
    float (*Ks)[KST] = (float(*)[KST])sm;
    float (*Vs)[KST] = (float(*)[KST])(sm + AR * KST);
    float (*Ps)[64]  = (float(*)[64])(sm + 2 * AR * KST);

    const int s0 = blockIdx.x * 32;
    const int h  = blockIdx.y;
    const int b  = blockIdx.z;
    const int tid = threadIdx.x;
    const int base = (b * SEQ) * HS + h * HD;

    for (int i = tid; i < AR * 16; i += 1024) {
        int r = i >> 4, c4 = (i & 15) * 4;
        int j = s0 - HALF + r;
        float4 kv = make_float4(0.f, 0.f, 0.f, 0.f), vv = kv;
        if (j >= 0 && j < SEQ) {
            int off = base + j * HS + c4;
            kv = *(const float4*)&g_k[off];
            vv = *(const float4*)&g_v[off];
        }
        *(float4*)&Ks[r][c4] = kv;
        *(float4*)&Vs[r][c4] = vv;
    }
    __syncthreads();

    const int wq   = tid >> 5;
    const int lane = tid & 31;
    const float* qrow = g_q + base + (s0 + wq) * HS;

    float sc0 = 0.f, sc1 = 0.f;
    #pragma unroll
    for (int d4 = 0; d4 < 16; d4++) {
        float4 q  = __ldg((const float4*)(qrow + d4 * 4));
        float4 k0 = *(const float4*)&Ks[wq + lane][d4 * 4];
        float4 k1 = *(const float4*)&Ks[wq + lane + 32][d4 * 4];
        sc0 += q.x * k0.x + q.y * k0.y + q.z * k0.z + q.w * k0.w;
        sc1 += q.x * k1.x + q.y * k1.y + q.z * k1.z + q.w * k1.w;
    }
    sc0 *= 0.125f;
    sc1 *= 0.125f;

    float m = fmaxf(sc0, sc1);
    #pragma unroll
    for (int o = 16; o; o >>= 1) m = fmaxf(m, __shfl_xor_sync(0xFFFFFFFFu, m, o));
    float e0 = __expf(sc0 - m);
    float e1 = __expf(sc1 - m);
    float sum = e0 + e1;
    #pragma unroll
    for (int o = 16; o; o >>= 1) sum += __shfl_xor_sync(0xFFFFFFFFu, sum, o);
    float inv = 1.f / sum;
    Ps[wq][lane]      = e0 * inv;
    Ps[wq][lane + 32] = e1 * inv;
    __syncwarp();

    float c0 = 0.f, c1 = 0.f;
    #pragma unroll
    for (int w = 0; w < 64; w++) {
        float p = Ps[wq][w];
        float2 v = *(const float2*)&Vs[wq + w][2 * lane];
        c0 += p * v.x;
        c1 += p * v.y;
    }
    const int orow = base + (s0 + wq) * HS + 2 * lane;
    __nv_bfloat162 hi2, lo2;
    hi2.x = __float2bfloat16(c0);
    hi2.y = __float2bfloat16(c1);
    lo2.x = __float2bfloat16(c0 - __bfloat162float(hi2.x));
    lo2.y = __float2bfloat16(c1 - __bfloat162float(hi2.y));
    *(__nv_bfloat162*)&g_chi[orow] = hi2;
    *(__nv_bfloat162*)&g_clo[orow] = lo2;
}

// ---------------------------------------------------------------------------
extern "C" void kernel_launch(void* const* d_in, const int* in_sizes, int n_in,
                              void* d_out, int out_size)
{
    const float* X  = (const float*)d_in[0];
    const float* Wq = (const float*)d_in[1];
    const float* bq = (const float*)d_in[2];
    const float* Wk = (const float*)d_in[3];
    const float* bk = (const float*)d_in[4];
    const float* Wv = (const float*)d_in[5];
    const float* bv = (const float*)d_in[6];
    const float* Wo = (const float*)d_in[7];
    const float* bo = (const float*)d_in[8];
    float* out = (float*)d_out;

    static bool attr_done = false;
    if (!attr_done) {
        cudaFuncSetAttribute(qkv_kernel,  cudaFuncAttributeMaxDynamicSharedMemorySize, SMEM_QKV);
        cudaFuncSetAttribute(out_kernel,  cudaFuncAttributeMaxDynamicSharedMemorySize, SMEM_OUT);
        cudaFuncSetAttribute(attn_kernel, cudaFuncAttributeMaxDynamicSharedMemorySize, SMEM_ATTN);
        attr_done = true;
    }

    split_kernel<<<1024, 256>>>(X, Wq, Wk, Wv, Wo);

    dim3 qkv_grid(HS / 256, MTOK / 128, 3);    // (3, 16, 3) = 144 ~ one wave
    qkv_kernel<<<qkv_grid, 256, SMEM_QKV>>>(bq, bk, bv);

    dim3 attn_grid(SEQ / 32, NH, BATCH);       // (32, 12, 2)
    attn_kernel<<<attn_grid, 1024, SMEM_ATTN>>>();

    dim3 out_grid(HS / 96, MTOK / 64, 1);      // (8, 32) = 256, single wave
    out_kernel<<<out_grid, 192, SMEM_OUT>>>(bo, out);
}